// round 10
// baseline (speedup 1.0000x reference)
#include <cuda_runtime.h>
#include <cuda_bf16.h>
#include <cuda_fp16.h>
#include <math.h>
#include <stdint.h>

#define NN 100000
#define NE 1600000
#define DH 128
#define DO 64

// ---------------- device scratch (static; no allocation allowed) ----------------
__device__ int      g_deg[NN];
__device__ int      g_fill[NN];
__device__ int      g_rowptr[NN];
__device__ int      g_csr[NE];
__device__ uint4    g_z4[(size_t)NN * DH * 2 / 16];   // fp16 Z backing
__device__ float4   g_h4[(size_t)NN * DH / 4];        // fp32 H backing
__device__ int      g_bsums[128];
__device__ uint32_t g_wbh[128 * 64];   // packed bf16x2 hi, paired LDS.64 order
__device__ uint32_t g_wbl[128 * 64];   // packed bf16x2 lo

// ---------------- bf16 split helpers ----------------
__device__ __forceinline__ void split2(float x, float y, uint32_t& hp, uint32_t& lp) {
    __nv_bfloat16 hx = __float2bfloat16(x);
    __nv_bfloat16 hy = __float2bfloat16(y);
    __nv_bfloat16 lx = __float2bfloat16(x - __bfloat162float(hx));
    __nv_bfloat16 ly = __float2bfloat16(y - __bfloat162float(hy));
    hp = ((uint32_t)__bfloat16_as_ushort(hy) << 16) | (uint32_t)__bfloat16_as_ushort(hx);
    lp = ((uint32_t)__bfloat16_as_ushort(ly) << 16) | (uint32_t)__bfloat16_as_ushort(lx);
}

__device__ __forceinline__ void mma_bf16(float* c, const uint32_t* a, uint32_t b0, uint32_t b1) {
    asm volatile(
        "mma.sync.aligned.m16n8k16.row.col.f32.bf16.bf16.f32 "
        "{%0,%1,%2,%3}, {%4,%5,%6,%7}, {%8,%9}, {%0,%1,%2,%3};"
        : "+f"(c[0]), "+f"(c[1]), "+f"(c[2]), "+f"(c[3])
        : "r"(a[0]), "r"(a[1]), "r"(a[2]), "r"(a[3]), "r"(b0), "r"(b1));
}

// paired position for word kp: fragment words (ak, ak+4) become adjacent
__device__ __forceinline__ int ppos(int kp) {
    int ks = kp >> 3, q = kp & 7;
    return ks * 8 + ((q < 4) ? q * 2 : (q - 4) * 2 + 1);
}

// ---------------- prep kernels ----------------
__global__ void k_zero() {
    int i = blockIdx.x * 256 + threadIdx.x;
    if (i < NN) { g_deg[i] = 0; g_fill[i] = 0; }
}
__global__ void k_hist(const int* __restrict__ dst) {
    int i = blockIdx.x * 256 + threadIdx.x;
    if (i < NE) atomicAdd(&g_deg[dst[i]], 1);
}
__global__ void k_scan1() {
    __shared__ int s[1024];
    int t = threadIdx.x;
    int i = blockIdx.x * 1024 + t;
    int val = (i < NN) ? g_deg[i] : 0;
    s[t] = val;
    __syncthreads();
    for (int off = 1; off < 1024; off <<= 1) {
        int x = (t >= off) ? s[t - off] : 0;
        __syncthreads();
        if (t >= off) s[t] += x;
        __syncthreads();
    }
    if (i < NN) g_rowptr[i] = s[t] - val;
    if (t == 1023) g_bsums[blockIdx.x] = s[1023];
}
__global__ void k_scan2(int nb) {
    __shared__ int s[128];
    int t = threadIdx.x;
    int v = (t < nb) ? g_bsums[t] : 0;
    s[t] = v;
    __syncthreads();
    for (int off = 1; off < 128; off <<= 1) {
        int x = (t >= off) ? s[t - off] : 0;
        __syncthreads();
        if (t >= off) s[t] += x;
        __syncthreads();
    }
    if (t < nb) g_bsums[t] = s[t] - v;  // exclusive
}
__global__ void k_scan3() {
    int i = blockIdx.x * 1024 + threadIdx.x;
    if (i < NN) g_rowptr[i] += g_bsums[blockIdx.x];
}
__global__ void k_csr(const int* __restrict__ src, const int* __restrict__ dst) {
    int i = blockIdx.x * 256 + threadIdx.x;
    if (i < NE) {
        int d = dst[i];
        int pos = g_rowptr[d] + atomicAdd(&g_fill[d], 1);
        g_csr[pos] = src[i];
    }
}

// ---------------- weight pack: fp32 -> bf16x2 hi/lo, paired LDS.64 order ----------------
__global__ void k_wconv(const float* __restrict__ W, int outc) {
    int i = blockIdx.x * 256 + threadIdx.x;
    if (i >= outc * 64) return;
    int col = i >> 6, kp = i & 63;
    float w0 = W[(2 * kp) * outc + col];
    float w1 = W[(2 * kp + 1) * outc + col];
    uint32_t hp, lp;
    split2(w0, w1, hp, lp);
    g_wbh[col * 64 + ppos(kp)] = hp;
    g_wbl[col * 64 + ppos(kp)] = lp;
}

// ---------------- mma.sync GEMM: Z[v][t] = dinv[v] * dot(X[v,:], W[:,t]) ----------------
// M-tile 64, block 256 (8 warps): warp = (m-frag mh 0..3) x (N-half nh 0..1).
// A staged in smem: coalesced LDG.128 from X, bf16 hi/lo split once, paired stride-72
// layout -> all fragment loads are LDS.64 (same pattern as B). 3-pass split precision.
template <int OUTC>
__global__ void __launch_bounds__(256, 2) k_gemm(const float* __restrict__ X,
                                                 __half* __restrict__ Z) {
    extern __shared__ uint32_t sm[];
    uint32_t* Ash = sm;                 // 64*72
    uint32_t* Asl = Ash + 64 * 72;
    uint32_t* Bsh = Asl + 64 * 72;      // OUTC*72
    uint32_t* Bsl = Bsh + OUTC * 72;
    int tid = threadIdx.x;
    int base = blockIdx.x * 64;

    // stage B from packed global (uint4 copies, pad 64 -> 72 stride)
    {
        const uint4* gh = (const uint4*)g_wbh;
        const uint4* gl = (const uint4*)g_wbl;
        for (int i = tid; i < OUTC * 16; i += 256) {
            int col = i >> 4, q = i & 15;
            *(uint4*)&Bsh[col * 72 + q * 4] = gh[i];
            *(uint4*)&Bsl[col * 72 + q * 4] = gl[i];
        }
    }
    // stage A: 64 rows x 32 float4 (fully coalesced), split + paired store
    {
#pragma unroll
        for (int it = 0; it < 8; it++) {
            int i = tid + it * 256;          // 0..2047
            int row = i >> 5, c = i & 31;
            int v = base + row;
            float4 x = (v < NN) ? *(const float4*)(X + (size_t)v * DH + c * 4)
                                : make_float4(0.f, 0.f, 0.f, 0.f);
            uint32_t h0, l0, h1, l1;
            split2(x.x, x.y, h0, l0);
            split2(x.z, x.w, h1, l1);
            int p0 = ppos(2 * c), p1 = ppos(2 * c + 1);
            Ash[row * 72 + p0] = h0; Asl[row * 72 + p0] = l0;
            Ash[row * 72 + p1] = h1; Asl[row * 72 + p1] = l1;
        }
    }
    __syncthreads();

    int wid = tid >> 5, lane = tid & 31;
    int gp = lane >> 2, qp = lane & 3;
    int mh = wid & 3, nh = wid >> 2;
    int r0 = mh * 16 + gp;
    int v0 = base + r0, v8 = v0 + 8;
    bool q0 = v0 < NN, q8 = v8 < NN;

    constexpr int NJ = OUTC / 16;       // j-tiles per warp (N-half)
    constexpr int NB = OUTC / 2;        // N-half width
    float acc[NJ][4];
#pragma unroll
    for (int j = 0; j < NJ; j++) {
        acc[j][0] = 0.f; acc[j][1] = 0.f; acc[j][2] = 0.f; acc[j][3] = 0.f;
    }

#pragma unroll
    for (int ks = 0; ks < 8; ks++) {
        int fo = ks * 8 + qp * 2;
        uint2 h0 = *(const uint2*)&Ash[r0 * 72 + fo];
        uint2 h1 = *(const uint2*)&Ash[(r0 + 8) * 72 + fo];
        uint2 l0 = *(const uint2*)&Asl[r0 * 72 + fo];
        uint2 l1 = *(const uint2*)&Asl[(r0 + 8) * 72 + fo];
        uint32_t ah[4] = {h0.x, h1.x, h0.y, h1.y};
        uint32_t al[4] = {l0.x, l1.x, l0.y, l1.y};
#pragma unroll
        for (int j = 0; j < NJ; j++) {
            int c = (nh * NB + j * 8 + gp) * 72 + fo;
            uint2 bh = *(const uint2*)&Bsh[c];
            uint2 bl = *(const uint2*)&Bsl[c];
            mma_bf16(acc[j], ah, bh.x, bh.y);
            mma_bf16(acc[j], ah, bl.x, bl.y);
            mma_bf16(acc[j], al, bh.x, bh.y);
        }
    }

    // epilogue: dinv from degree, scale, store fp16
    float d0 = q0 ? rsqrtf((float)g_deg[v0] + 1.f) : 0.f;
    float d8 = q8 ? rsqrtf((float)g_deg[v8] + 1.f) : 0.f;
#pragma unroll
    for (int j = 0; j < NJ; j++) {
        int col = nh * NB + j * 8 + qp * 2;
        if (q0)
            *(__half2*)(Z + (size_t)v0 * OUTC + col) =
                __float22half2_rn(make_float2(d0 * acc[j][0], d0 * acc[j][1]));
        if (q8)
            *(__half2*)(Z + (size_t)v8 * OUTC + col) =
                __float22half2_rn(make_float2(d8 * acc[j][2], d8 * acc[j][3]));
    }
}

// ---------------- aggregation (unchanged: 1 row/load, 8-deep MLP) ----------------
template <int VPT>
__device__ __forceinline__ void ld_row(uint32_t* r, const __half* __restrict__ Z,
                                       int s, int lane) {
    const char* p = (const char*)(Z) + ((size_t)s * (VPT * 32) + lane * VPT) * 2;
    if (VPT == 4) {
        uint2 x = *(const uint2*)p;
        r[0] = x.x; r[1] = x.y;
    } else {
        r[0] = *(const uint32_t*)p;
    }
}
template <int VPT>
__device__ __forceinline__ void acc_row(float* acc, const uint32_t* r) {
#pragma unroll
    for (int q = 0; q < VPT / 2; q++) {
        float2 f = __half22float2(*(const __half2*)&r[q]);
        acc[2 * q] += f.x;
        acc[2 * q + 1] += f.y;
    }
}

template <int OUTC, bool RELU, bool LSM>
__global__ void k_agg(const __half* __restrict__ Z, const float* __restrict__ bias,
                      float* __restrict__ out) {
    int v = (blockIdx.x * blockDim.x + threadIdx.x) >> 5;
    if (v >= NN) return;
    int lane = threadIdx.x & 31;
    constexpr int VPT = OUTC / 32;
    float acc[VPT];
#pragma unroll
    for (int i = 0; i < VPT; i++) acc[i] = 0.f;

    // self term
    {
        uint32_t r[VPT / 2];
        ld_row<VPT>(r, Z, v, lane);
        acc_row<VPT>(acc, r);
    }

    int start = g_rowptr[v];
    int cnt = g_deg[v];
    int e = 0;
    for (; e + 8 <= cnt; e += 8) {   // 8 independent gathers in flight
        int s0 = g_csr[start + e + 0];
        int s1 = g_csr[start + e + 1];
        int s2 = g_csr[start + e + 2];
        int s3 = g_csr[start + e + 3];
        int s4 = g_csr[start + e + 4];
        int s5 = g_csr[start + e + 5];
        int s6 = g_csr[start + e + 6];
        int s7 = g_csr[start + e + 7];
        uint32_t r0[VPT / 2], r1[VPT / 2], r2[VPT / 2], r3[VPT / 2];
        uint32_t r4[VPT / 2], r5[VPT / 2], r6[VPT / 2], r7[VPT / 2];
        ld_row<VPT>(r0, Z, s0, lane);
        ld_row<VPT>(r1, Z, s1, lane);
        ld_row<VPT>(r2, Z, s2, lane);
        ld_row<VPT>(r3, Z, s3, lane);
        ld_row<VPT>(r4, Z, s4, lane);
        ld_row<VPT>(r5, Z, s5, lane);
        ld_row<VPT>(r6, Z, s6, lane);
        ld_row<VPT>(r7, Z, s7, lane);
        acc_row<VPT>(acc, r0);
        acc_row<VPT>(acc, r1);
        acc_row<VPT>(acc, r2);
        acc_row<VPT>(acc, r3);
        acc_row<VPT>(acc, r4);
        acc_row<VPT>(acc, r5);
        acc_row<VPT>(acc, r6);
        acc_row<VPT>(acc, r7);
    }
    if (e + 4 <= cnt) {
        int s0 = g_csr[start + e + 0];
        int s1 = g_csr[start + e + 1];
        int s2 = g_csr[start + e + 2];
        int s3 = g_csr[start + e + 3];
        uint32_t r0[VPT / 2], r1[VPT / 2], r2[VPT / 2], r3[VPT / 2];
        ld_row<VPT>(r0, Z, s0, lane);
        ld_row<VPT>(r1, Z, s1, lane);
        ld_row<VPT>(r2, Z, s2, lane);
        ld_row<VPT>(r3, Z, s3, lane);
        acc_row<VPT>(acc, r0);
        acc_row<VPT>(acc, r1);
        acc_row<VPT>(acc, r2);
        acc_row<VPT>(acc, r3);
        e += 4;
    }
    for (; e < cnt; e++) {
        uint32_t r[VPT / 2];
        ld_row<VPT>(r, Z, g_csr[start + e], lane);
        acc_row<VPT>(acc, r);
    }

    float dv = rsqrtf((float)cnt + 1.f);
    float h[VPT];
#pragma unroll
    for (int i = 0; i < VPT; i++) {
        h[i] = fmaf(dv, acc[i], bias[lane * VPT + i]);
        if (RELU) h[i] = fmaxf(h[i], 0.f);
    }
    if (LSM) {
        float m = h[0];
#pragma unroll
        for (int i = 1; i < VPT; i++) m = fmaxf(m, h[i]);
#pragma unroll
        for (int off = 16; off > 0; off >>= 1)
            m = fmaxf(m, __shfl_xor_sync(0xffffffffu, m, off));
        float s = 0.f;
#pragma unroll
        for (int i = 0; i < VPT; i++) s += expf(h[i] - m);
#pragma unroll
        for (int off = 16; off > 0; off >>= 1)
            s += __shfl_xor_sync(0xffffffffu, s, off);
        float l = m + logf(s);
#pragma unroll
        for (int i = 0; i < VPT; i++) h[i] -= l;
    }
    float* op = out + (size_t)v * OUTC + lane * VPT;
    if (VPT == 4) {
        *(float4*)op = make_float4(h[0], h[1], h[2], h[3]);
    } else {
        *(float2*)op = make_float2(h[0], h[1]);
    }
}

// ---------------- launch ----------------
extern "C" void kernel_launch(void* const* d_in, const int* in_sizes, int n_in,
                              void* d_out, int out_size) {
    const int*   edges = (const int*)d_in[0];
    const int*   esrc  = edges;
    const int*   edst  = edges + NE;
    const float* X  = (const float*)d_in[1];
    const float* W0 = (const float*)d_in[2];
    const float* b0 = (const float*)d_in[3];
    const float* W1 = (const float*)d_in[4];
    const float* b1 = (const float*)d_in[5];
    const float* W2 = (const float*)d_in[6];
    const float* b2 = (const float*)d_in[7];
    float* out = (float*)d_out;

    __half* zp;
    float*  hp;
    cudaGetSymbolAddress((void**)&zp, g_z4);
    cudaGetSymbolAddress((void**)&hp, g_h4);

    const int SMEM_A    = 64 * 72 * 2 * 4;              // 36864
    const int SMEM_G128 = SMEM_A + DH * 72 * 2 * 4;     // 110592
    const int SMEM_G64  = SMEM_A + DO * 72 * 2 * 4;     // 73728
    cudaFuncSetAttribute(k_gemm<DH>, cudaFuncAttributeMaxDynamicSharedMemorySize, SMEM_G128);
    cudaFuncSetAttribute(k_gemm<DO>, cudaFuncAttributeMaxDynamicSharedMemorySize, SMEM_G64);

    const int scan_blocks = (NN + 1023) / 1024;   // 98
    const int gemm_blocks = (NN + 63) / 64;       // 1563
    const int agg_blocks  = NN / 8;               // 12500

    // launch order puts gemm L1 at slot 4 (profiled by ncu -s 5 -c 1)
    k_wconv<<<(DH * 64 + 255) / 256, 256>>>(W0, DH);          // 1
    k_zero<<<(NN + 255) / 256, 256>>>();                      // 2
    k_hist<<<(NE + 255) / 256, 256>>>(edst);                  // 3 (deg ready)
    k_gemm<DH><<<gemm_blocks, 256, SMEM_G128>>>(X, zp);       // 4 <- profiled
    k_scan1<<<scan_blocks, 1024>>>();                         // 5
    k_scan2<<<1, 128>>>(scan_blocks);                         // 6
    k_scan3<<<scan_blocks, 1024>>>();                         // 7
    k_csr<<<(NE + 255) / 256, 256>>>(esrc, edst);             // 8

    // layer 1 agg
    k_agg<DH, true, false><<<agg_blocks, 256>>>(zp, b0, hp);

    // layer 2
    k_wconv<<<(DH * 64 + 255) / 256, 256>>>(W1, DH);
    k_gemm<DH><<<gemm_blocks, 256, SMEM_G128>>>(hp, zp);
    k_agg<DH, true, false><<<agg_blocks, 256>>>(zp, b1, hp);

    // layer 3 + log_softmax
    k_wconv<<<(DO * 64 + 255) / 256, 256>>>(W2, DO);
    k_gemm<DO><<<gemm_blocks, 256, SMEM_G64>>>(hp, zp);
    k_agg<DO, false, true><<<agg_blocks, 256>>>(zp, b2, out);
}

// round 11
// speedup vs baseline: 1.7952x; 1.7952x over previous
#include <cuda_runtime.h>
#include <cuda_fp16.h>
#include <math.h>
#include <stdint.h>

#define NN 100000
#define NE 1600000
#define DH 128
#define DO 64

// ---------------- device scratch (static; no allocation allowed) ----------------
__device__ int      g_deg[NN];
__device__ int      g_fill[NN];
__device__ int      g_rowptr[NN];
__device__ int      g_csr[NE];
__device__ uint4    g_z4[(size_t)NN * DH * 2 / 16];   // fp16 Z backing
__device__ float4   g_h4[(size_t)NN * DH / 4];        // fp32 H backing
__device__ int      g_bsums[128];
__device__ uint32_t g_wb[128 * 64];   // packed fp16x2 weights, paired LDS.64 order

// ---------------- helpers ----------------
__device__ __forceinline__ uint32_t packh2(float x, float y) {
    __half2 h = __floats2half2_rn(x, y);
    return *(uint32_t*)&h;
}

__device__ __forceinline__ void mma_f16(float* c, const uint32_t* a, uint32_t b0, uint32_t b1) {
    asm volatile(
        "mma.sync.aligned.m16n8k16.row.col.f32.f16.f16.f32 "
        "{%0,%1,%2,%3}, {%4,%5,%6,%7}, {%8,%9}, {%0,%1,%2,%3};"
        : "+f"(c[0]), "+f"(c[1]), "+f"(c[2]), "+f"(c[3])
        : "r"(a[0]), "r"(a[1]), "r"(a[2]), "r"(a[3]), "r"(b0), "r"(b1));
}

// paired position for word kp: fragment words (ak, ak+4) become adjacent
__device__ __forceinline__ int ppos(int kp) {
    int ks = kp >> 3, q = kp & 7;
    return ks * 8 + ((q < 4) ? q * 2 : (q - 4) * 2 + 1);
}

// ---------------- prep kernels ----------------
__global__ void k_zero() {
    int i = blockIdx.x * 256 + threadIdx.x;
    if (i < NN) { g_deg[i] = 0; g_fill[i] = 0; }
}
__global__ void k_hist(const int* __restrict__ dst) {
    int i = blockIdx.x * 256 + threadIdx.x;
    if (i < NE) atomicAdd(&g_deg[dst[i]], 1);
}
__global__ void k_scan1() {
    __shared__ int s[1024];
    int t = threadIdx.x;
    int i = blockIdx.x * 1024 + t;
    int val = (i < NN) ? g_deg[i] : 0;
    s[t] = val;
    __syncthreads();
    for (int off = 1; off < 1024; off <<= 1) {
        int x = (t >= off) ? s[t - off] : 0;
        __syncthreads();
        if (t >= off) s[t] += x;
        __syncthreads();
    }
    if (i < NN) g_rowptr[i] = s[t] - val;
    if (t == 1023) g_bsums[blockIdx.x] = s[1023];
}
__global__ void k_scan2(int nb) {
    __shared__ int s[128];
    int t = threadIdx.x;
    int v = (t < nb) ? g_bsums[t] : 0;
    s[t] = v;
    __syncthreads();
    for (int off = 1; off < 128; off <<= 1) {
        int x = (t >= off) ? s[t - off] : 0;
        __syncthreads();
        if (t >= off) s[t] += x;
        __syncthreads();
    }
    if (t < nb) g_bsums[t] = s[t] - v;  // exclusive
}
__global__ void k_scan3() {
    int i = blockIdx.x * 1024 + threadIdx.x;
    if (i < NN) g_rowptr[i] += g_bsums[blockIdx.x];
}
__global__ void k_csr(const int* __restrict__ src, const int* __restrict__ dst) {
    int i = blockIdx.x * 256 + threadIdx.x;
    if (i < NE) {
        int d = dst[i];
        int pos = g_rowptr[d] + atomicAdd(&g_fill[d], 1);
        g_csr[pos] = src[i];
    }
}

// ---------------- weight pack: fp32 -> fp16x2, paired LDS.64 order ----------------
__global__ void k_wconv(const float* __restrict__ W, int outc) {
    int i = blockIdx.x * 256 + threadIdx.x;
    if (i >= outc * 64) return;
    int col = i >> 6, kp = i & 63;
    float w0 = W[(2 * kp) * outc + col];
    float w1 = W[(2 * kp + 1) * outc + col];
    g_wb[col * 64 + ppos(kp)] = packh2(w0, w1);
}

// ---------------- mma.sync GEMM: Z[v][t] = dinv[v] * dot(X[v,:], W[:,t]) ----------------
// M-tile 64, block 256 (8 warps): warp = (m-frag mh 0..3) x (N-half nh 0..1).
// Single-pass fp16 mma, fp32 accumulate. A fragments straight from global X
// (guarded float2 -> half2 in regs); B in smem, stride 72 paired -> LDS.64.
template <int OUTC>
__global__ void __launch_bounds__(256, 3) k_gemm(const float* __restrict__ X,
                                                 __half* __restrict__ Z) {
    extern __shared__ uint32_t sm[];
    uint32_t* Bs = sm;                  // OUTC*72 words
    int tid = threadIdx.x;
    int base = blockIdx.x * 64;

    // stage B from packed global (uint4 copies, pad 64 -> 72 stride)
    {
        const uint4* gw = (const uint4*)g_wb;
        for (int i = tid; i < OUTC * 16; i += 256) {
            int col = i >> 4, q = i & 15;
            *(uint4*)&Bs[col * 72 + q * 4] = gw[i];
        }
    }
    __syncthreads();

    int wid = tid >> 5, lane = tid & 31;
    int gp = lane >> 2, qp = lane & 3;
    int mh = wid & 3, nh = wid >> 2;
    int r0 = mh * 16 + gp;
    int v0 = base + r0, v8 = v0 + 8;
    bool q0 = v0 < NN, q8 = v8 < NN;
    const float* x0 = X + (size_t)v0 * DH;
    const float* x8 = X + (size_t)v8 * DH;

    constexpr int NJ = OUTC / 16;       // j-tiles per warp (N-half)
    constexpr int NB = OUTC / 2;        // N-half width
    float acc[NJ][4];
#pragma unroll
    for (int j = 0; j < NJ; j++) {
        acc[j][0] = 0.f; acc[j][1] = 0.f; acc[j][2] = 0.f; acc[j][3] = 0.f;
    }

#pragma unroll
    for (int ks = 0; ks < 8; ks++) {
        int ak = ks * 8 + qp;
        float2 z2 = make_float2(0.f, 0.f);
        float2 p00 = q0 ? *(const float2*)(x0 + 2 * ak) : z2;
        float2 p02 = q0 ? *(const float2*)(x0 + 2 * ak + 8) : z2;
        float2 p10 = q8 ? *(const float2*)(x8 + 2 * ak) : z2;
        float2 p12 = q8 ? *(const float2*)(x8 + 2 * ak + 8) : z2;
        uint32_t a[4];
        a[0] = packh2(p00.x, p00.y);
        a[1] = packh2(p10.x, p10.y);
        a[2] = packh2(p02.x, p02.y);
        a[3] = packh2(p12.x, p12.y);
#pragma unroll
        for (int j = 0; j < NJ; j++) {
            int c = (nh * NB + j * 8 + gp) * 72 + ks * 8 + qp * 2;
            uint2 b = *(const uint2*)&Bs[c];
            mma_f16(acc[j], a, b.x, b.y);
        }
    }

    // epilogue: dinv from degree, scale, store fp16
    float d0 = q0 ? rsqrtf((float)g_deg[v0] + 1.f) : 0.f;
    float d8 = q8 ? rsqrtf((float)g_deg[v8] + 1.f) : 0.f;
#pragma unroll
    for (int j = 0; j < NJ; j++) {
        int col = nh * NB + j * 8 + qp * 2;
        if (q0)
            *(__half2*)(Z + (size_t)v0 * OUTC + col) =
                __float22half2_rn(make_float2(d0 * acc[j][0], d0 * acc[j][1]));
        if (q8)
            *(__half2*)(Z + (size_t)v8 * OUTC + col) =
                __float22half2_rn(make_float2(d8 * acc[j][2], d8 * acc[j][3]));
    }
}

// ---------------- aggregation (unchanged: 1 row/load, 8-deep MLP) ----------------
template <int VPT>
__device__ __forceinline__ void ld_row(uint32_t* r, const __half* __restrict__ Z,
                                       int s, int lane) {
    const char* p = (const char*)(Z) + ((size_t)s * (VPT * 32) + lane * VPT) * 2;
    if (VPT == 4) {
        uint2 x = *(const uint2*)p;
        r[0] = x.x; r[1] = x.y;
    } else {
        r[0] = *(const uint32_t*)p;
    }
}
template <int VPT>
__device__ __forceinline__ void acc_row(float* acc, const uint32_t* r) {
#pragma unroll
    for (int q = 0; q < VPT / 2; q++) {
        float2 f = __half22float2(*(const __half2*)&r[q]);
        acc[2 * q] += f.x;
        acc[2 * q + 1] += f.y;
    }
}

template <int OUTC, bool RELU, bool LSM>
__global__ void k_agg(const __half* __restrict__ Z, const float* __restrict__ bias,
                      float* __restrict__ out) {
    int v = (blockIdx.x * blockDim.x + threadIdx.x) >> 5;
    if (v >= NN) return;
    int lane = threadIdx.x & 31;
    constexpr int VPT = OUTC / 32;
    float acc[VPT];
#pragma unroll
    for (int i = 0; i < VPT; i++) acc[i] = 0.f;

    // self term
    {
        uint32_t r[VPT / 2];
        ld_row<VPT>(r, Z, v, lane);
        acc_row<VPT>(acc, r);
    }

    int start = g_rowptr[v];
    int cnt = g_deg[v];
    int e = 0;
    for (; e + 8 <= cnt; e += 8) {   // 8 independent gathers in flight
        int s0 = g_csr[start + e + 0];
        int s1 = g_csr[start + e + 1];
        int s2 = g_csr[start + e + 2];
        int s3 = g_csr[start + e + 3];
        int s4 = g_csr[start + e + 4];
        int s5 = g_csr[start + e + 5];
        int s6 = g_csr[start + e + 6];
        int s7 = g_csr[start + e + 7];
        uint32_t r0[VPT / 2], r1[VPT / 2], r2[VPT / 2], r3[VPT / 2];
        uint32_t r4[VPT / 2], r5[VPT / 2], r6[VPT / 2], r7[VPT / 2];
        ld_row<VPT>(r0, Z, s0, lane);
        ld_row<VPT>(r1, Z, s1, lane);
        ld_row<VPT>(r2, Z, s2, lane);
        ld_row<VPT>(r3, Z, s3, lane);
        ld_row<VPT>(r4, Z, s4, lane);
        ld_row<VPT>(r5, Z, s5, lane);
        ld_row<VPT>(r6, Z, s6, lane);
        ld_row<VPT>(r7, Z, s7, lane);
        acc_row<VPT>(acc, r0);
        acc_row<VPT>(acc, r1);
        acc_row<VPT>(acc, r2);
        acc_row<VPT>(acc, r3);
        acc_row<VPT>(acc, r4);
        acc_row<VPT>(acc, r5);
        acc_row<VPT>(acc, r6);
        acc_row<VPT>(acc, r7);
    }
    if (e + 4 <= cnt) {
        int s0 = g_csr[start + e + 0];
        int s1 = g_csr[start + e + 1];
        int s2 = g_csr[start + e + 2];
        int s3 = g_csr[start + e + 3];
        uint32_t r0[VPT / 2], r1[VPT / 2], r2[VPT / 2], r3[VPT / 2];
        ld_row<VPT>(r0, Z, s0, lane);
        ld_row<VPT>(r1, Z, s1, lane);
        ld_row<VPT>(r2, Z, s2, lane);
        ld_row<VPT>(r3, Z, s3, lane);
        acc_row<VPT>(acc, r0);
        acc_row<VPT>(acc, r1);
        acc_row<VPT>(acc, r2);
        acc_row<VPT>(acc, r3);
        e += 4;
    }
    for (; e < cnt; e++) {
        uint32_t r[VPT / 2];
        ld_row<VPT>(r, Z, g_csr[start + e], lane);
        acc_row<VPT>(acc, r);
    }

    float dv = rsqrtf((float)cnt + 1.f);
    float h[VPT];
#pragma unroll
    for (int i = 0; i < VPT; i++) {
        h[i] = fmaf(dv, acc[i], bias[lane * VPT + i]);
        if (RELU) h[i] = fmaxf(h[i], 0.f);
    }
    if (LSM) {
        float m = h[0];
#pragma unroll
        for (int i = 1; i < VPT; i++) m = fmaxf(m, h[i]);
#pragma unroll
        for (int off = 16; off > 0; off >>= 1)
            m = fmaxf(m, __shfl_xor_sync(0xffffffffu, m, off));
        float s = 0.f;
#pragma unroll
        for (int i = 0; i < VPT; i++) s += expf(h[i] - m);
#pragma unroll
        for (int off = 16; off > 0; off >>= 1)
            s += __shfl_xor_sync(0xffffffffu, s, off);
        float l = m + logf(s);
#pragma unroll
        for (int i = 0; i < VPT; i++) h[i] -= l;
    }
    float* op = out + (size_t)v * OUTC + lane * VPT;
    if (VPT == 4) {
        *(float4*)op = make_float4(h[0], h[1], h[2], h[3]);
    } else {
        *(float2*)op = make_float2(h[0], h[1]);
    }
}

// ---------------- launch ----------------
extern "C" void kernel_launch(void* const* d_in, const int* in_sizes, int n_in,
                              void* d_out, int out_size) {
    const int*   edges = (const int*)d_in[0];
    const int*   esrc  = edges;
    const int*   edst  = edges + NE;
    const float* X  = (const float*)d_in[1];
    const float* W0 = (const float*)d_in[2];
    const float* b0 = (const float*)d_in[3];
    const float* W1 = (const float*)d_in[4];
    const float* b1 = (const float*)d_in[5];
    const float* W2 = (const float*)d_in[6];
    const float* b2 = (const float*)d_in[7];
    float* out = (float*)d_out;

    __half* zp;
    float*  hp;
    cudaGetSymbolAddress((void**)&zp, g_z4);
    cudaGetSymbolAddress((void**)&hp, g_h4);

    const int SMEM_G128 = DH * 72 * 4;  // 36864
    const int SMEM_G64  = DO * 72 * 4;  // 18432
    cudaFuncSetAttribute(k_gemm<DH>, cudaFuncAttributeMaxDynamicSharedMemorySize, SMEM_G128);
    cudaFuncSetAttribute(k_gemm<DO>, cudaFuncAttributeMaxDynamicSharedMemorySize, SMEM_G64);

    const int scan_blocks = (NN + 1023) / 1024;   // 98
    const int gemm_blocks = (NN + 63) / 64;       // 1563
    const int agg_blocks  = NN / 8;               // 12500

    // launch order puts gemm L1 at slot 4 (profiled by ncu -s 5 -c 1)
    k_wconv<<<(DH * 64 + 255) / 256, 256>>>(W0, DH);          // 1
    k_zero<<<(NN + 255) / 256, 256>>>();                      // 2
    k_hist<<<(NE + 255) / 256, 256>>>(edst);                  // 3 (deg ready)
    k_gemm<DH><<<gemm_blocks, 256, SMEM_G128>>>(X, zp);       // 4 <- profiled
    k_scan1<<<scan_blocks, 1024>>>();                         // 5
    k_scan2<<<1, 128>>>(scan_blocks);                         // 6
    k_scan3<<<scan_blocks, 1024>>>();                         // 7
    k_csr<<<(NE + 255) / 256, 256>>>(esrc, edst);             // 8

    // layer 1 agg
    k_agg<DH, true, false><<<agg_blocks, 256>>>(zp, b0, hp);

    // layer 2
    k_wconv<<<(DH * 64 + 255) / 256, 256>>>(W1, DH);
    k_gemm<DH><<<gemm_blocks, 256, SMEM_G128>>>(hp, zp);
    k_agg<DH, true, false><<<agg_blocks, 256>>>(zp, b1, hp);

    // layer 3 + log_softmax
    k_wconv<<<(DO * 64 + 255) / 256, 256>>>(W2, DO);
    k_gemm<DO><<<gemm_blocks, 256, SMEM_G64>>>(hp, zp);
    k_agg<DO, false, true><<<agg_blocks, 256>>>(zp, b2, out);
}

// round 12
// speedup vs baseline: 1.9648x; 1.0945x over previous
#include <cuda_runtime.h>
#include <cuda_fp16.h>
#include <math.h>
#include <stdint.h>

#define NN 100000
#define NE 1600000
#define DH 128
#define DO 64

// ---------------- device scratch (static; no allocation allowed) ----------------
__device__ int      g_deg[NN];
__device__ int      g_fill[NN];
__device__ int      g_rowptr[NN];
__device__ int      g_csr[NE];
__device__ uint4    g_z4[(size_t)NN * DH * 2 / 16];   // fp16 Z backing
__device__ float4   g_h4[(size_t)NN * DH / 4];        // fp32 H backing
__device__ int      g_bsums[128];
__device__ uint32_t g_wb[128 * 64];   // packed fp16x2 weights, paired LDS.64 order

// ---------------- helpers ----------------
__device__ __forceinline__ uint32_t packh2(float x, float y) {
    __half2 h = __floats2half2_rn(x, y);
    return *(uint32_t*)&h;
}

__device__ __forceinline__ void mma_f16(float* c, const uint32_t* a, uint32_t b0, uint32_t b1) {
    asm volatile(
        "mma.sync.aligned.m16n8k16.row.col.f32.f16.f16.f32 "
        "{%0,%1,%2,%3}, {%4,%5,%6,%7}, {%8,%9}, {%0,%1,%2,%3};"
        : "+f"(c[0]), "+f"(c[1]), "+f"(c[2]), "+f"(c[3])
        : "r"(a[0]), "r"(a[1]), "r"(a[2]), "r"(a[3]), "r"(b0), "r"(b1));
}

// paired position for word kp: fragment words (ak, ak+4) become adjacent
__device__ __forceinline__ int ppos(int kp) {
    int ks = kp >> 3, q = kp & 7;
    return ks * 8 + ((q < 4) ? q * 2 : (q - 4) * 2 + 1);
}

// ---------------- prep kernels ----------------
__global__ void k_zero() {
    int i = blockIdx.x * 256 + threadIdx.x;
    if (i < NN) { g_deg[i] = 0; g_fill[i] = 0; }
}
__global__ void k_hist(const int* __restrict__ dst) {
    int i = blockIdx.x * 256 + threadIdx.x;
    if (i < NE) atomicAdd(&g_deg[dst[i]], 1);
}
__global__ void k_scan1() {
    __shared__ int s[1024];
    int t = threadIdx.x;
    int i = blockIdx.x * 1024 + t;
    int val = (i < NN) ? g_deg[i] : 0;
    s[t] = val;
    __syncthreads();
    for (int off = 1; off < 1024; off <<= 1) {
        int x = (t >= off) ? s[t - off] : 0;
        __syncthreads();
        if (t >= off) s[t] += x;
        __syncthreads();
    }
    if (i < NN) g_rowptr[i] = s[t] - val;
    if (t == 1023) g_bsums[blockIdx.x] = s[1023];
}
__global__ void k_scan2(int nb) {
    __shared__ int s[128];
    int t = threadIdx.x;
    int v = (t < nb) ? g_bsums[t] : 0;
    s[t] = v;
    __syncthreads();
    for (int off = 1; off < 128; off <<= 1) {
        int x = (t >= off) ? s[t - off] : 0;
        __syncthreads();
        if (t >= off) s[t] += x;
        __syncthreads();
    }
    if (t < nb) g_bsums[t] = s[t] - v;  // exclusive
}
__global__ void k_scan3() {
    int i = blockIdx.x * 1024 + threadIdx.x;
    if (i < NN) g_rowptr[i] += g_bsums[blockIdx.x];
}
__global__ void k_csr(const int* __restrict__ src, const int* __restrict__ dst) {
    int i = blockIdx.x * 256 + threadIdx.x;
    if (i < NE) {
        int d = dst[i];
        int pos = g_rowptr[d] + atomicAdd(&g_fill[d], 1);
        g_csr[pos] = src[i];
    }
}

// ---------------- weight pack: fp32 -> fp16x2, paired LDS.64 order ----------------
__global__ void k_wconv(const float* __restrict__ W, int outc) {
    int i = blockIdx.x * 256 + threadIdx.x;
    if (i >= outc * 64) return;
    int col = i >> 6, kp = i & 63;
    float w0 = W[(2 * kp) * outc + col];
    float w1 = W[(2 * kp + 1) * outc + col];
    g_wb[col * 64 + ppos(kp)] = packh2(w0, w1);
}

// ---------------- mma.sync GEMM: Z[v][t] = dinv[v] * dot(X[v,:], W[:,t]) ----------------
// M-tile 128, block 256 (8 warps): warp wid owns m-frag rows wid*16..+15, FULL N.
// No A duplication across warps (each A row loaded exactly once per CTA).
// A fragments from global (guarded float2 -> half2 in regs), software-pipelined
// one ks ahead. B in smem, stride 72 paired -> LDS.64. Single-pass fp16 mma.
template <int OUTC>
__global__ void __launch_bounds__(256, 2) k_gemm(const float* __restrict__ X,
                                                 __half* __restrict__ Z) {
    extern __shared__ uint32_t sm[];
    uint32_t* Bs = sm;                  // OUTC*72 words
    int tid = threadIdx.x;
    int base = blockIdx.x * 128;

    // stage B from packed global (uint4 copies, pad 64 -> 72 stride)
    {
        const uint4* gw = (const uint4*)g_wb;
        for (int i = tid; i < OUTC * 16; i += 256) {
            int col = i >> 4, q = i & 15;
            *(uint4*)&Bs[col * 72 + q * 4] = gw[i];
        }
    }
    __syncthreads();

    int wid = tid >> 5, lane = tid & 31;
    int gp = lane >> 2, qp = lane & 3;
    int r0 = wid * 16 + gp;
    int v0 = base + r0, v8 = v0 + 8;
    bool q0 = v0 < NN, q8 = v8 < NN;
    const float* x0 = X + (size_t)v0 * DH;
    const float* x8 = X + (size_t)v8 * DH;

    constexpr int NJ = OUTC / 8;        // n-tiles per warp (full N)
    float acc[NJ][4];
#pragma unroll
    for (int j = 0; j < NJ; j++) {
        acc[j][0] = 0.f; acc[j][1] = 0.f; acc[j][2] = 0.f; acc[j][3] = 0.f;
    }

    const float2 z2 = make_float2(0.f, 0.f);
    // prologue: A fragments for ks=0
    float2 c00 = q0 ? *(const float2*)(x0 + 2 * qp) : z2;
    float2 c02 = q0 ? *(const float2*)(x0 + 2 * qp + 8) : z2;
    float2 c10 = q8 ? *(const float2*)(x8 + 2 * qp) : z2;
    float2 c12 = q8 ? *(const float2*)(x8 + 2 * qp + 8) : z2;

#pragma unroll
    for (int ks = 0; ks < 8; ks++) {
        float2 n00 = z2, n02 = z2, n10 = z2, n12 = z2;
        if (ks < 7) {
            int ak = (ks + 1) * 8 + qp;
            n00 = q0 ? *(const float2*)(x0 + 2 * ak) : z2;
            n02 = q0 ? *(const float2*)(x0 + 2 * ak + 8) : z2;
            n10 = q8 ? *(const float2*)(x8 + 2 * ak) : z2;
            n12 = q8 ? *(const float2*)(x8 + 2 * ak + 8) : z2;
        }
        uint32_t a[4];
        a[0] = packh2(c00.x, c00.y);
        a[1] = packh2(c10.x, c10.y);
        a[2] = packh2(c02.x, c02.y);
        a[3] = packh2(c12.x, c12.y);
#pragma unroll
        for (int j = 0; j < NJ; j++) {
            int c = (j * 8 + gp) * 72 + ks * 8 + qp * 2;
            uint2 b = *(const uint2*)&Bs[c];
            mma_f16(acc[j], a, b.x, b.y);
        }
        c00 = n00; c02 = n02; c10 = n10; c12 = n12;
    }

    // epilogue: dinv from degree, scale, store fp16
    float d0 = q0 ? rsqrtf((float)g_deg[v0] + 1.f) : 0.f;
    float d8 = q8 ? rsqrtf((float)g_deg[v8] + 1.f) : 0.f;
#pragma unroll
    for (int j = 0; j < NJ; j++) {
        int col = j * 8 + qp * 2;
        if (q0)
            *(__half2*)(Z + (size_t)v0 * OUTC + col) =
                __float22half2_rn(make_float2(d0 * acc[j][0], d0 * acc[j][1]));
        if (q8)
            *(__half2*)(Z + (size_t)v8 * OUTC + col) =
                __float22half2_rn(make_float2(d8 * acc[j][2], d8 * acc[j][3]));
    }
}

// ---------------- aggregation (unchanged: 1 row/load, 8-deep MLP) ----------------
template <int VPT>
__device__ __forceinline__ void ld_row(uint32_t* r, const __half* __restrict__ Z,
                                       int s, int lane) {
    const char* p = (const char*)(Z) + ((size_t)s * (VPT * 32) + lane * VPT) * 2;
    if (VPT == 4) {
        uint2 x = *(const uint2*)p;
        r[0] = x.x; r[1] = x.y;
    } else {
        r[0] = *(const uint32_t*)p;
    }
}
template <int VPT>
__device__ __forceinline__ void acc_row(float* acc, const uint32_t* r) {
#pragma unroll
    for (int q = 0; q < VPT / 2; q++) {
        float2 f = __half22float2(*(const __half2*)&r[q]);
        acc[2 * q] += f.x;
        acc[2 * q + 1] += f.y;
    }
}

template <int OUTC, bool RELU, bool LSM>
__global__ void k_agg(const __half* __restrict__ Z, const float* __restrict__ bias,
                      float* __restrict__ out) {
    int v = (blockIdx.x * blockDim.x + threadIdx.x) >> 5;
    if (v >= NN) return;
    int lane = threadIdx.x & 31;
    constexpr int VPT = OUTC / 32;
    float acc[VPT];
#pragma unroll
    for (int i = 0; i < VPT; i++) acc[i] = 0.f;

    // self term
    {
        uint32_t r[VPT / 2];
        ld_row<VPT>(r, Z, v, lane);
        acc_row<VPT>(acc, r);
    }

    int start = g_rowptr[v];
    int cnt = g_deg[v];
    int e = 0;
    for (; e + 8 <= cnt; e += 8) {   // 8 independent gathers in flight
        int s0 = g_csr[start + e + 0];
        int s1 = g_csr[start + e + 1];
        int s2 = g_csr[start + e + 2];
        int s3 = g_csr[start + e + 3];
        int s4 = g_csr[start + e + 4];
        int s5 = g_csr[start + e + 5];
        int s6 = g_csr[start + e + 6];
        int s7 = g_csr[start + e + 7];
        uint32_t r0[VPT / 2], r1[VPT / 2], r2[VPT / 2], r3[VPT / 2];
        uint32_t r4[VPT / 2], r5[VPT / 2], r6[VPT / 2], r7[VPT / 2];
        ld_row<VPT>(r0, Z, s0, lane);
        ld_row<VPT>(r1, Z, s1, lane);
        ld_row<VPT>(r2, Z, s2, lane);
        ld_row<VPT>(r3, Z, s3, lane);
        ld_row<VPT>(r4, Z, s4, lane);
        ld_row<VPT>(r5, Z, s5, lane);
        ld_row<VPT>(r6, Z, s6, lane);
        ld_row<VPT>(r7, Z, s7, lane);
        acc_row<VPT>(acc, r0);
        acc_row<VPT>(acc, r1);
        acc_row<VPT>(acc, r2);
        acc_row<VPT>(acc, r3);
        acc_row<VPT>(acc, r4);
        acc_row<VPT>(acc, r5);
        acc_row<VPT>(acc, r6);
        acc_row<VPT>(acc, r7);
    }
    if (e + 4 <= cnt) {
        int s0 = g_csr[start + e + 0];
        int s1 = g_csr[start + e + 1];
        int s2 = g_csr[start + e + 2];
        int s3 = g_csr[start + e + 3];
        uint32_t r0[VPT / 2], r1[VPT / 2], r2[VPT / 2], r3[VPT / 2];
        ld_row<VPT>(r0, Z, s0, lane);
        ld_row<VPT>(r1, Z, s1, lane);
        ld_row<VPT>(r2, Z, s2, lane);
        ld_row<VPT>(r3, Z, s3, lane);
        acc_row<VPT>(acc, r0);
        acc_row<VPT>(acc, r1);
        acc_row<VPT>(acc, r2);
        acc_row<VPT>(acc, r3);
        e += 4;
    }
    for (; e < cnt; e++) {
        uint32_t r[VPT / 2];
        ld_row<VPT>(r, Z, g_csr[start + e], lane);
        acc_row<VPT>(acc, r);
    }

    float dv = rsqrtf((float)cnt + 1.f);
    float h[VPT];
#pragma unroll
    for (int i = 0; i < VPT; i++) {
        h[i] = fmaf(dv, acc[i], bias[lane * VPT + i]);
        if (RELU) h[i] = fmaxf(h[i], 0.f);
    }
    if (LSM) {
        float m = h[0];
#pragma unroll
        for (int i = 1; i < VPT; i++) m = fmaxf(m, h[i]);
#pragma unroll
        for (int off = 16; off > 0; off >>= 1)
            m = fmaxf(m, __shfl_xor_sync(0xffffffffu, m, off));
        float s = 0.f;
#pragma unroll
        for (int i = 0; i < VPT; i++) s += expf(h[i] - m);
#pragma unroll
        for (int off = 16; off > 0; off >>= 1)
            s += __shfl_xor_sync(0xffffffffu, s, off);
        float l = m + logf(s);
#pragma unroll
        for (int i = 0; i < VPT; i++) h[i] -= l;
    }
    float* op = out + (size_t)v * OUTC + lane * VPT;
    if (VPT == 4) {
        *(float4*)op = make_float4(h[0], h[1], h[2], h[3]);
    } else {
        *(float2*)op = make_float2(h[0], h[1]);
    }
}

// ---------------- launch ----------------
extern "C" void kernel_launch(void* const* d_in, const int* in_sizes, int n_in,
                              void* d_out, int out_size) {
    const int*   edges = (const int*)d_in[0];
    const int*   esrc  = edges;
    const int*   edst  = edges + NE;
    const float* X  = (const float*)d_in[1];
    const float* W0 = (const float*)d_in[2];
    const float* b0 = (const float*)d_in[3];
    const float* W1 = (const float*)d_in[4];
    const float* b1 = (const float*)d_in[5];
    const float* W2 = (const float*)d_in[6];
    const float* b2 = (const float*)d_in[7];
    float* out = (float*)d_out;

    __half* zp;
    float*  hp;
    cudaGetSymbolAddress((void**)&zp, g_z4);
    cudaGetSymbolAddress((void**)&hp, g_h4);

    const int SMEM_G128 = DH * 72 * 4;  // 36864
    const int SMEM_G64  = DO * 72 * 4;  // 18432
    cudaFuncSetAttribute(k_gemm<DH>, cudaFuncAttributeMaxDynamicSharedMemorySize, SMEM_G128);
    cudaFuncSetAttribute(k_gemm<DO>, cudaFuncAttributeMaxDynamicSharedMemorySize, SMEM_G64);

    const int scan_blocks = (NN + 1023) / 1024;   // 98
    const int gemm_blocks = (NN + 127) / 128;     // 782
    const int agg_blocks  = NN / 8;               // 12500

    // launch order puts gemm L1 at slot 4 (profiled by ncu -s 5 -c 1)
    k_wconv<<<(DH * 64 + 255) / 256, 256>>>(W0, DH);          // 1
    k_zero<<<(NN + 255) / 256, 256>>>();                      // 2
    k_hist<<<(NE + 255) / 256, 256>>>(edst);                  // 3 (deg ready)
    k_gemm<DH><<<gemm_blocks, 256, SMEM_G128>>>(X, zp);       // 4 <- profiled
    k_scan1<<<scan_blocks, 1024>>>();                         // 5
    k_scan2<<<1, 128>>>(scan_blocks);                         // 6
    k_scan3<<<scan_blocks, 1024>>>();                         // 7
    k_csr<<<(NE + 255) / 256, 256>>>(esrc, edst);             // 8

    // layer 1 agg
    k_agg<DH, true, false><<<agg_blocks, 256>>>(zp, b0, hp);

    // layer 2
    k_wconv<<<(DH * 64 + 255) / 256, 256>>>(W1, DH);
    k_gemm<DH><<<gemm_blocks, 256, SMEM_G128>>>(hp, zp);
    k_agg<DH, true, false><<<agg_blocks, 256>>>(zp, b1, hp);

    // layer 3 + log_softmax
    k_wconv<<<(DO * 64 + 255) / 256, 256>>>(W2, DO);
    k_gemm<DO><<<gemm_blocks, 256, SMEM_G64>>>(hp, zp);
    k_agg<DO, false, true><<<agg_blocks, 256>>>(zp, b2, out);
}

// round 14
// speedup vs baseline: 2.0632x; 1.0501x over previous
#include <cuda_runtime.h>
#include <cuda_fp16.h>
#include <math.h>
#include <stdint.h>

#define NN 100000
#define NE 1600000
#define DH 128
#define DO 64

// ---------------- device scratch (static; no allocation allowed) ----------------
__device__ int      g_deg[NN];
__device__ int      g_fill[NN];
__device__ int      g_rowptr[NN];
__device__ int      g_csr[NE];
__device__ uint4    g_z4[(size_t)NN * DH * 2 / 16];   // fp16 Z backing
__device__ uint4    g_hh[(size_t)NN * DH * 2 / 16];   // fp16 H backing
__device__ int      g_bsums[128];
__device__ uint32_t g_wb[128 * 64];   // packed fp16x2 weights, natural k-pair order

// ---------------- helpers ----------------
__device__ __forceinline__ uint32_t packh2(float x, float y) {
    __half2 h = __floats2half2_rn(x, y);
    return *(uint32_t*)&h;
}

__device__ __forceinline__ void mma_f16(float* c, const uint32_t* a, uint32_t b0, uint32_t b1) {
    asm volatile(
        "mma.sync.aligned.m16n8k16.row.col.f32.f16.f16.f32 "
        "{%0,%1,%2,%3}, {%4,%5,%6,%7}, {%8,%9}, {%0,%1,%2,%3};"
        : "+f"(c[0]), "+f"(c[1]), "+f"(c[2]), "+f"(c[3])
        : "r"(a[0]), "r"(a[1]), "r"(a[2]), "r"(a[3]), "r"(b0), "r"(b1));
}

// ---------------- prep kernels ----------------
__global__ void k_zero() {
    int i = blockIdx.x * 256 + threadIdx.x;
    if (i < NN) { g_deg[i] = 0; g_fill[i] = 0; }
}
__global__ void k_hist(const int* __restrict__ dst) {
    int i = blockIdx.x * 256 + threadIdx.x;
    if (i < NE) atomicAdd(&g_deg[dst[i]], 1);
}
__global__ void k_scan1() {
    __shared__ int s[1024];
    int t = threadIdx.x;
    int i = blockIdx.x * 1024 + t;
    int val = (i < NN) ? g_deg[i] : 0;
    s[t] = val;
    __syncthreads();
    for (int off = 1; off < 1024; off <<= 1) {
        int x = (t >= off) ? s[t - off] : 0;
        __syncthreads();
        if (t >= off) s[t] += x;
        __syncthreads();
    }
    if (i < NN) g_rowptr[i] = s[t] - val;
    if (t == 1023) g_bsums[blockIdx.x] = s[1023];
}
__global__ void k_scan2(int nb) {
    __shared__ int s[128];
    int t = threadIdx.x;
    int v = (t < nb) ? g_bsums[t] : 0;
    s[t] = v;
    __syncthreads();
    for (int off = 1; off < 128; off <<= 1) {
        int x = (t >= off) ? s[t - off] : 0;
        __syncthreads();
        if (t >= off) s[t] += x;
        __syncthreads();
    }
    if (t < nb) g_bsums[t] = s[t] - v;  // exclusive
}
__global__ void k_scan3() {
    int i = blockIdx.x * 1024 + threadIdx.x;
    if (i < NN) g_rowptr[i] += g_bsums[blockIdx.x];
}
__global__ void k_csr(const int* __restrict__ src, const int* __restrict__ dst) {
    int i = blockIdx.x * 256 + threadIdx.x;
    if (i < NE) {
        int d = dst[i];
        int pos = g_rowptr[d] + atomicAdd(&g_fill[d], 1);
        g_csr[pos] = src[i];
    }
}

// ---------------- weight pack: fp32 -> fp16x2, natural k-pair order ----------------
// With the k-permutation (logical {2qp,2qp+1,2qp+8,2qp+9} = physical {4qp..4qp+3}),
// fragment words are just consecutive natural pairs.
__global__ void k_wconv(const float* __restrict__ W, int outc) {
    int i = blockIdx.x * 256 + threadIdx.x;
    if (i >= outc * 64) return;
    int col = i >> 6, kp = i & 63;
    g_wb[col * 64 + kp] = packh2(W[(2 * kp) * outc + col], W[(2 * kp + 1) * outc + col]);
}

// ---------------- mma.sync GEMM: Z[v][t] = dinv[v] * dot(X[v,:], W[:,t]) ----------------
// M-tile 128, block 256 (8 warps): warp wid owns rows wid*16..+15, FULL N.
// k-permuted fragments: thread qp owns physical k {16ks+4qp..+3} ->
//   fp32 A: ONE float4 per row per ks;  fp16 A: ONE uint2 per row per ks.
// B in smem stride 72, natural order -> LDS.64 per fragment. Single-pass fp16 mma.
template <int OUTC, bool AHALF>
__global__ void __launch_bounds__(256, 2) k_gemm(const void* __restrict__ Xv,
                                                 __half* __restrict__ Z) {
    extern __shared__ uint32_t sm[];
    uint32_t* Bs = sm;                  // OUTC*72 words
    int tid = threadIdx.x;
    int base = blockIdx.x * 128;

    // stage B from packed global (uint4 copies, pad 64 -> 72 stride)
    {
        const uint4* gw = (const uint4*)g_wb;
        for (int i = tid; i < OUTC * 16; i += 256) {
            int col = i >> 4, q = i & 15;
            *(uint4*)&Bs[col * 72 + q * 4] = gw[i];
        }
    }
    __syncthreads();

    int wid = tid >> 5, lane = tid & 31;
    int gp = lane >> 2, qp = lane & 3;
    int r0 = wid * 16 + gp;
    int v0 = base + r0, v8 = v0 + 8;
    bool q0 = v0 < NN, q8 = v8 < NN;

    constexpr int NJ = OUTC / 8;        // n-tiles per warp (full N)
    float acc[NJ][4];
#pragma unroll
    for (int j = 0; j < NJ; j++) {
        acc[j][0] = 0.f; acc[j][1] = 0.f; acc[j][2] = 0.f; acc[j][3] = 0.f;
    }

    if (AHALF) {
        const uint2* x0 = (const uint2*)((const __half*)Xv + (size_t)v0 * DH);
        const uint2* x8 = (const uint2*)((const __half*)Xv + (size_t)v8 * DH);
        uint2 zu = make_uint2(0u, 0u);
        uint2 c0 = q0 ? x0[qp] : zu;
        uint2 c1 = q8 ? x8[qp] : zu;
#pragma unroll
        for (int ks = 0; ks < 8; ks++) {
            uint2 n0 = zu, n1 = zu;
            if (ks < 7) {
                int idx = (ks + 1) * 4 + qp;
                n0 = q0 ? x0[idx] : zu;
                n1 = q8 ? x8[idx] : zu;
            }
            uint32_t a[4] = {c0.x, c1.x, c0.y, c1.y};
#pragma unroll
            for (int j = 0; j < NJ; j++) {
                int c = (j * 8 + gp) * 72 + ks * 8 + qp * 2;
                uint2 b = *(const uint2*)&Bs[c];
                mma_f16(acc[j], a, b.x, b.y);
            }
            c0 = n0; c1 = n1;
        }
    } else {
        const float4* x0 = (const float4*)((const float*)Xv + (size_t)v0 * DH);
        const float4* x8 = (const float4*)((const float*)Xv + (size_t)v8 * DH);
        float4 zf = make_float4(0.f, 0.f, 0.f, 0.f);
        float4 c0 = q0 ? x0[qp] : zf;
        float4 c1 = q8 ? x8[qp] : zf;
#pragma unroll
        for (int ks = 0; ks < 8; ks++) {
            float4 n0 = zf, n1 = zf;
            if (ks < 7) {
                int idx = (ks + 1) * 4 + qp;
                n0 = q0 ? x0[idx] : zf;
                n1 = q8 ? x8[idx] : zf;
            }
            uint32_t a[4];
            a[0] = packh2(c0.x, c0.y);
            a[1] = packh2(c1.x, c1.y);
            a[2] = packh2(c0.z, c0.w);
            a[3] = packh2(c1.z, c1.w);
#pragma unroll
            for (int j = 0; j < NJ; j++) {
                int c = (j * 8 + gp) * 72 + ks * 8 + qp * 2;
                uint2 b = *(const uint2*)&Bs[c];
                mma_f16(acc[j], a, b.x, b.y);
            }
            c0 = n0; c1 = n1;
        }
    }

    // epilogue: dinv from degree, scale, store fp16
    float d0 = q0 ? rsqrtf((float)g_deg[v0] + 1.f) : 0.f;
    float d8 = q8 ? rsqrtf((float)g_deg[v8] + 1.f) : 0.f;
#pragma unroll
    for (int j = 0; j < NJ; j++) {
        int col = j * 8 + qp * 2;
        if (q0)
            *(__half2*)(Z + (size_t)v0 * OUTC + col) =
                __float22half2_rn(make_float2(d0 * acc[j][0], d0 * acc[j][1]));
        if (q8)
            *(__half2*)(Z + (size_t)v8 * OUTC + col) =
                __float22half2_rn(make_float2(d8 * acc[j][2], d8 * acc[j][3]));
    }
}

// ---------------- aggregation: 1 row/load, 8-deep MLP; optional fp16 output ----------------
template <int VPT>
__device__ __forceinline__ void ld_row(uint32_t* r, const __half* __restrict__ Z,
                                       int s, int lane) {
    const char* p = (const char*)(Z) + ((size_t)s * (VPT * 32) + lane * VPT) * 2;
    if (VPT == 4) {
        uint2 x = *(const uint2*)p;
        r[0] = x.x; r[1] = x.y;
    } else {
        r[0] = *(const uint32_t*)p;
    }
}
template <int VPT>
__device__ __forceinline__ void acc_row(float* acc, const uint32_t* r) {
#pragma unroll
    for (int q = 0; q < VPT / 2; q++) {
        float2 f = __half22float2(*(const __half2*)&r[q]);
        acc[2 * q] += f.x;
        acc[2 * q + 1] += f.y;
    }
}

template <int OUTC, bool RELU, bool LSM, bool HOUT>
__global__ void k_agg(const __half* __restrict__ Z, const float* __restrict__ bias,
                      void* __restrict__ outv) {
    int v = (blockIdx.x * blockDim.x + threadIdx.x) >> 5;
    if (v >= NN) return;
    int lane = threadIdx.x & 31;
    constexpr int VPT = OUTC / 32;
    float acc[VPT];
#pragma unroll
    for (int i = 0; i < VPT; i++) acc[i] = 0.f;

    // self term
    {
        uint32_t r[VPT / 2];
        ld_row<VPT>(r, Z, v, lane);
        acc_row<VPT>(acc, r);
    }

    int start = g_rowptr[v];
    int cnt = g_deg[v];
    int e = 0;
    for (; e + 8 <= cnt; e += 8) {   // 8 independent gathers in flight
        int s0 = g_csr[start + e + 0];
        int s1 = g_csr[start + e + 1];
        int s2 = g_csr[start + e + 2];
        int s3 = g_csr[start + e + 3];
        int s4 = g_csr[start + e + 4];
        int s5 = g_csr[start + e + 5];
        int s6 = g_csr[start + e + 6];
        int s7 = g_csr[start + e + 7];
        uint32_t r0[VPT / 2], r1[VPT / 2], r2[VPT / 2], r3[VPT / 2];
        uint32_t r4[VPT / 2], r5[VPT / 2], r6[VPT / 2], r7[VPT / 2];
        ld_row<VPT>(r0, Z, s0, lane);
        ld_row<VPT>(r1, Z, s1, lane);
        ld_row<VPT>(r2, Z, s2, lane);
        ld_row<VPT>(r3, Z, s3, lane);
        ld_row<VPT>(r4, Z, s4, lane);
        ld_row<VPT>(r5, Z, s5, lane);
        ld_row<VPT>(r6, Z, s6, lane);
        ld_row<VPT>(r7, Z, s7, lane);
        acc_row<VPT>(acc, r0);
        acc_row<VPT>(acc, r1);
        acc_row<VPT>(acc, r2);
        acc_row<VPT>(acc, r3);
        acc_row<VPT>(acc, r4);
        acc_row<VPT>(acc, r5);
        acc_row<VPT>(acc, r6);
        acc_row<VPT>(acc, r7);
    }
    if (e + 4 <= cnt) {
        int s0 = g_csr[start + e + 0];
        int s1 = g_csr[start + e + 1];
        int s2 = g_csr[start + e + 2];
        int s3 = g_csr[start + e + 3];
        uint32_t r0[VPT / 2], r1[VPT / 2], r2[VPT / 2], r3[VPT / 2];
        ld_row<VPT>(r0, Z, s0, lane);
        ld_row<VPT>(r1, Z, s1, lane);
        ld_row<VPT>(r2, Z, s2, lane);
        ld_row<VPT>(r3, Z, s3, lane);
        acc_row<VPT>(acc, r0);
        acc_row<VPT>(acc, r1);
        acc_row<VPT>(acc, r2);
        acc_row<VPT>(acc, r3);
        e += 4;
    }
    for (; e < cnt; e++) {
        uint32_t r[VPT / 2];
        ld_row<VPT>(r, Z, g_csr[start + e], lane);
        acc_row<VPT>(acc, r);
    }

    float dv = rsqrtf((float)cnt + 1.f);
    float h[VPT];
#pragma unroll
    for (int i = 0; i < VPT; i++) {
        h[i] = fmaf(dv, acc[i], bias[lane * VPT + i]);
        if (RELU) h[i] = fmaxf(h[i], 0.f);
    }
    if (LSM) {
        float m = h[0];
#pragma unroll
        for (int i = 1; i < VPT; i++) m = fmaxf(m, h[i]);
#pragma unroll
        for (int off = 16; off > 0; off >>= 1)
            m = fmaxf(m, __shfl_xor_sync(0xffffffffu, m, off));
        float s = 0.f;
#pragma unroll
        for (int i = 0; i < VPT; i++) s += expf(h[i] - m);
#pragma unroll
        for (int off = 16; off > 0; off >>= 1)
            s += __shfl_xor_sync(0xffffffffu, s, off);
        float l = m + logf(s);
#pragma unroll
        for (int i = 0; i < VPT; i++) h[i] -= l;
    }

    if (HOUT) {
        // fp16 intermediate H
        __half* op = (__half*)outv + (size_t)v * OUTC + lane * VPT;
        if (VPT == 4) {
            uint2 o;
            o.x = packh2(h[0], h[1]);
            o.y = packh2(h[2], h[3]);
            *(uint2*)op = o;
        } else {
            *(uint32_t*)op = packh2(h[0], h[1]);
        }
    } else {
        float* op = (float*)outv + (size_t)v * OUTC + lane * VPT;
        if (VPT == 4) {
            *(float4*)op = make_float4(h[0], h[1], h[2], h[3]);
        } else {
            *(float2*)op = make_float2(h[0], h[1]);
        }
    }
}

// ---------------- launch ----------------
extern "C" void kernel_launch(void* const* d_in, const int* in_sizes, int n_in,
                              void* d_out, int out_size) {
    const int*   edges = (const int*)d_in[0];
    const int*   esrc  = edges;
    const int*   edst  = edges + NE;
    const float* X  = (const float*)d_in[1];
    const float* W0 = (const float*)d_in[2];
    const float* b0 = (const float*)d_in[3];
    const float* W1 = (const float*)d_in[4];
    const float* b1 = (const float*)d_in[5];
    const float* W2 = (const float*)d_in[6];
    const float* b2 = (const float*)d_in[7];
    float* out = (float*)d_out;

    __half* zp;
    __half* hp;
    cudaGetSymbolAddress((void**)&zp, g_z4);
    cudaGetSymbolAddress((void**)&hp, g_hh);

    const int SMEM_G128 = DH * 72 * 4;  // 36864
    const int SMEM_G64  = DO * 72 * 4;  // 18432
    cudaFuncSetAttribute(k_gemm<DH, false>, cudaFuncAttributeMaxDynamicSharedMemorySize, SMEM_G128);
    cudaFuncSetAttribute(k_gemm<DH, true>,  cudaFuncAttributeMaxDynamicSharedMemorySize, SMEM_G128);
    cudaFuncSetAttribute(k_gemm<DO, true>,  cudaFuncAttributeMaxDynamicSharedMemorySize, SMEM_G64);

    const int scan_blocks = (NN + 1023) / 1024;   // 98
    const int gemm_blocks = (NN + 127) / 128;     // 782
    const int agg_blocks  = NN / 8;               // 12500

    // launch order puts gemm L1 at slot 4 (profiled by ncu -s 5 -c 1)
    k_wconv<<<(DH * 64 + 255) / 256, 256>>>(W0, DH);              // 1
    k_zero<<<(NN + 255) / 256, 256>>>();                          // 2
    k_hist<<<(NE + 255) / 256, 256>>>(edst);                      // 3 (deg ready)
    k_gemm<DH, false><<<gemm_blocks, 256, SMEM_G128>>>(X, zp);    // 4 <- profiled
    k_scan1<<<scan_blocks, 1024>>>();                             // 5
    k_scan2<<<1, 128>>>(scan_blocks);                             // 6
    k_scan3<<<scan_blocks, 1024>>>();                             // 7
    k_csr<<<(NE + 255) / 256, 256>>>(esrc, edst);                 // 8

    // layer 1 agg (fp16 H out)
    k_agg<DH, true, false, true><<<agg_blocks, 256>>>(zp, b0, hp);

    // layer 2 (fp16 A in)
    k_wconv<<<(DH * 64 + 255) / 256, 256>>>(W1, DH);
    k_gemm<DH, true><<<gemm_blocks, 256, SMEM_G128>>>(hp, zp);
    k_agg<DH, true, false, true><<<agg_blocks, 256>>>(zp, b1, hp);

    // layer 3 + log_softmax (fp32 out)
    k_wconv<<<(DO * 64 + 255) / 256, 256>>>(W2, DO);
    k_gemm<DO, true><<<gemm_blocks, 256, SMEM_G64>>>(hp, zp);
    k_agg<DO, false, true, false><<<agg_blocks, 256>>>(zp, b2, out);
}